// round 5
// baseline (speedup 1.0000x reference)
#include <cuda_runtime.h>
#include <cuda_bf16.h>
#include <cstdint>

// Problem constants
#define NQ    50000
#define MS    50000
#define HN    32
#define KKP   15
#define CINV  64
#define COUTV 128
#define KD    1024          // scratch row length (16 kp x 64 cin); >=960 is zero pad
#define KREAL 960
#define NPAD  50048         // 391 * 128
#define NITER 30            // 960 / 32

// ---------------------------------------------------------------------------
// Scratch (device globals; zero-initialized at load -> padding stays zero)
// ---------------------------------------------------------------------------
__device__ __nv_bfloat16 g_wfh[(size_t)NPAD * KD];   // wf hi  [n][kd]
__device__ __nv_bfloat16 g_wfl[(size_t)NPAD * KD];   // wf lo
__device__ __nv_bfloat16 g_wth[(size_t)COUTV * KD];  // W^T hi [cout][kd]
__device__ __nv_bfloat16 g_wtl[(size_t)COUTV * KD];  // W^T lo
__device__ __nv_bfloat16 g_xh[(size_t)MS * CINV];    // x hi [m][c]
__device__ __nv_bfloat16 g_xl[(size_t)MS * CINV];    // x lo

// ---------------------------------------------------------------------------
// mma / ldmatrix / cp.async helpers (baseline PTX features only)
// ---------------------------------------------------------------------------
__device__ __forceinline__ void ldsm4(uint32_t* r, uint32_t a) {
    asm volatile("ldmatrix.sync.aligned.m8n8.x4.shared.b16 {%0,%1,%2,%3}, [%4];"
                 : "=r"(r[0]), "=r"(r[1]), "=r"(r[2]), "=r"(r[3]) : "r"(a));
}
__device__ __forceinline__ void ldsm4t(uint32_t* r, uint32_t a) {
    asm volatile("ldmatrix.sync.aligned.m8n8.x4.trans.shared.b16 {%0,%1,%2,%3}, [%4];"
                 : "=r"(r[0]), "=r"(r[1]), "=r"(r[2]), "=r"(r[3]) : "r"(a));
}
__device__ __forceinline__ void ldsm2(uint32_t* r, uint32_t a) {
    asm volatile("ldmatrix.sync.aligned.m8n8.x2.shared.b16 {%0,%1}, [%2];"
                 : "=r"(r[0]), "=r"(r[1]) : "r"(a));
}
__device__ __forceinline__ void mma16816(float* c, const uint32_t* a, const uint32_t* b) {
    asm volatile(
        "mma.sync.aligned.m16n8k16.row.col.f32.bf16.bf16.f32 "
        "{%0,%1,%2,%3}, {%4,%5,%6,%7}, {%8,%9}, {%0,%1,%2,%3};"
        : "+f"(c[0]), "+f"(c[1]), "+f"(c[2]), "+f"(c[3])
        : "r"(a[0]), "r"(a[1]), "r"(a[2]), "r"(a[3]), "r"(b[0]), "r"(b[1]));
}
__device__ __forceinline__ void cp16(uint32_t saddr, const void* gaddr) {
    asm volatile("cp.async.cg.shared.global [%0], [%1], 16;"
                 :: "r"(saddr), "l"(gaddr) : "memory");
}

// ---------------------------------------------------------------------------
// Kernel 0a: weights -> W^T, bf16 hi/lo split.  Wt[cout][kd] = W[kd][cout]
// ---------------------------------------------------------------------------
__global__ __launch_bounds__(256) void kp_prep(const float* __restrict__ W) {
    const int id = blockIdx.x * 256 + threadIdx.x;       // 0 .. 131071
    const int kd = id & (KD - 1);
    const int n  = id >> 10;
    float v = (kd < KREAL) ? W[kd * COUTV + n] : 0.0f;
    __nv_bfloat16 h = __float2bfloat16_rn(v);
    __nv_bfloat16 l = __float2bfloat16_rn(v - __bfloat162float(h));
    g_wth[id] = h;
    g_wtl[id] = l;
}

// Kernel 0b: features -> bf16 hi/lo split
__global__ __launch_bounds__(256) void kp_prep_x(const float* __restrict__ x) {
    const int id = blockIdx.x * 256 + threadIdx.x;       // 0 .. 3.2M
    float v = x[id];
    __nv_bfloat16 h = __float2bfloat16_rn(v);
    __nv_bfloat16 l = __float2bfloat16_rn(v - __bfloat162float(h));
    g_xh[id] = h;
    g_xl[id] = l;
}

// ---------------------------------------------------------------------------
// Kernel 1: tensorized gather. One warp per query.
//   A = w[kp 16][h 32] (computed, hi/lo), B = x[h 32][c 64] (cp.async, hi/lo)
//   wf[16,64] = A @ B  via 48x mma.m16n8k16 (3-product split), fp32 acc.
// Per-warp private smem; no __syncthreads in the hot path.
// ---------------------------------------------------------------------------
#define XPITCH 144                 // 128B row + 16B pad (conflict-free ldsm)
#define WPITCH 80                  // 64B row + 16B pad
#define XBYTES (HN * XPITCH)       // 4608
#define WBYTES (16 * WPITCH)       // 1280
#define WSM    (2 * XBYTES + 2 * WBYTES)   // 11776 per warp
#define GSMEM  (8 * WSM)           // 94208 per block (8 warps)

__global__ __launch_bounds__(256) void kpconv_gather_mma(
    const float* __restrict__ q,
    const float* __restrict__ s,
    const int* __restrict__ nb,
    const float* __restrict__ kp)
{
    extern __shared__ char sm[];
    const int t    = threadIdx.x;
    const int lane = t & 31;
    const int wid  = t >> 5;
    const int n    = blockIdx.x * 8 + wid;

    char* wsm = sm + wid * WSM;
    const uint32_t xh_s = (uint32_t)__cvta_generic_to_shared(wsm);
    const uint32_t xl_s = xh_s + XBYTES;
    const uint32_t wh_s = xh_s + 2 * XBYTES;
    const uint32_t wl_s = wh_s + WBYTES;

    // neighbor index (clamped)
    int j = nb[(size_t)n * HN + lane];
    j = j < 0 ? 0 : (j >= MS ? MS - 1 : j);

    // cp.async: neighbor feature rows (bf16 hi/lo, 128B each) into [h][c] smem
    {
        const char* srch = (const char*)g_xh + (size_t)j * (CINV * 2);
        const char* srcl = (const char*)g_xl + (size_t)j * (CINV * 2);
        const uint32_t dh = xh_s + lane * XPITCH;
        const uint32_t dl = xl_s + lane * XPITCH;
#pragma unroll
        for (int c = 0; c < 8; c++) {
            cp16(dh + c * 16, srch + c * 16);
            cp16(dl + c * 16, srcl + c * 16);
        }
        asm volatile("cp.async.commit_group;" ::: "memory");
    }

    // influence weights for h = lane: w[k] = relu(1 - |p - kp_k| / 0.072)
    {
        const float qx = q[n * 3 + 0];
        const float qy = q[n * 3 + 1];
        const float qz = q[n * 3 + 2];
        const float nx = __ldg(&s[j * 3 + 0]) - qx;
        const float ny = __ldg(&s[j * 3 + 1]) - qy;
        const float nz = __ldg(&s[j * 3 + 2]) - qz;
        __nv_bfloat16* whp = reinterpret_cast<__nv_bfloat16*>(wsm + 2 * XBYTES);
        __nv_bfloat16* wlp = reinterpret_cast<__nv_bfloat16*>(wsm + 2 * XBYTES + WBYTES);
#pragma unroll
        for (int k = 0; k < KKP; k++) {
            const float dx = nx - __ldg(&kp[k * 3 + 0]);
            const float dy = ny - __ldg(&kp[k * 3 + 1]);
            const float dz = nz - __ldg(&kp[k * 3 + 2]);
            const float d2 = dx * dx + dy * dy + dz * dz;
            float w = 1.0f - sqrtf(d2) * (1.0f / 0.072f);
            w = w > 0.0f ? w : 0.0f;
            const __nv_bfloat16 h = __float2bfloat16_rn(w);
            const __nv_bfloat16 l = __float2bfloat16_rn(w - __bfloat162float(h));
            whp[(k * WPITCH) / 2 + lane] = h;
            wlp[(k * WPITCH) / 2 + lane] = l;
        }
        // zero pad row kp=15 (both halves): 16 lanes x 4B = 64B
        if (lane < 16) {
            *reinterpret_cast<uint32_t*>(wsm + 2 * XBYTES + 15 * WPITCH + lane * 4) = 0u;
            *reinterpret_cast<uint32_t*>(wsm + 2 * XBYTES + WBYTES + 15 * WPITCH + lane * 4) = 0u;
        }
    }
    asm volatile("cp.async.wait_group 0;" ::: "memory");
    __syncwarp();

    // A fragments: m16 k16 per chunk, non-trans ldsm4 (validated pattern)
    uint32_t a_h[2][4], a_l[2][4];
#pragma unroll
    for (int kc = 0; kc < 2; kc++) {
        const uint32_t ao = (lane & 15) * WPITCH + (lane >> 4) * 16 + kc * 32;
        ldsm4(a_h[kc], wh_s + ao);
        ldsm4(a_l[kc], wl_s + ao);
    }

    float acc[8][4];
#pragma unroll
    for (int an = 0; an < 8; an++)
#pragma unroll
        for (int e = 0; e < 4; e++) acc[an][e] = 0.0f;

    // B via ldmatrix.x4.trans from row-major [h][c]:
    // lanes 0-7 -> k0-7 @n0, 8-15 -> k8-15 @n0, 16-23 -> k0-7 @n8, 24-31 -> k8-15 @n8
    const uint32_t brow = ((lane >> 3) & 1) * 8 + (lane & 7);
    const uint32_t bcol = (lane >> 4) * 16;
#pragma unroll
    for (int kc = 0; kc < 2; kc++) {
#pragma unroll
        for (int nq = 0; nq < 4; nq++) {      // 16 columns per ldsm4.trans
            const uint32_t bo = (kc * 16 + brow) * XPITCH + bcol + nq * 32;
            uint32_t bh[4], bl[4];
            ldsm4t(bh, xh_s + bo);
            ldsm4t(bl, xl_s + bo);
#pragma unroll
            for (int nt = 0; nt < 2; nt++) {
                float* a = acc[nq * 2 + nt];
                mma16816(a, a_h[kc], bh + nt * 2);
                mma16816(a, a_h[kc], bl + nt * 2);
                mma16816(a, a_l[kc], bh + nt * 2);
            }
        }
    }

    // epilogue: acc(row kp = lane>>2 (+8), col c = an*8 + (lane&3)*2) -> bf16 hi/lo
    uint32_t* uh = reinterpret_cast<uint32_t*>(g_wfh);
    uint32_t* ul = reinterpret_cast<uint32_t*>(g_wfl);
    const int kp0 = lane >> 2;
    const int cb  = (lane & 3) * 2;
#pragma unroll
    for (int an = 0; an < 8; an++) {
        const int c = an * 8 + cb;
#pragma unroll
        for (int half = 0; half < 2; half++) {
            const float v0 = acc[an][half * 2 + 0];
            const float v1 = acc[an][half * 2 + 1];
            const __nv_bfloat16 h0 = __float2bfloat16_rn(v0);
            const __nv_bfloat16 h1 = __float2bfloat16_rn(v1);
            const __nv_bfloat16 l0 = __float2bfloat16_rn(v0 - __bfloat162float(h0));
            const __nv_bfloat16 l1 = __float2bfloat16_rn(v1 - __bfloat162float(h1));
            __nv_bfloat162 ph; ph.x = h0; ph.y = h1;
            __nv_bfloat162 pl; pl.x = l0; pl.y = l1;
            const size_t off = ((size_t)n * KD + (kp0 + half * 8) * 64 + c) >> 1;
            uh[off] = *reinterpret_cast<uint32_t*>(&ph);
            ul[off] = *reinterpret_cast<uint32_t*>(&pl);
        }
    }
}

// ---------------------------------------------------------------------------
// Kernel 2: bf16 mma.sync GEMM  out[N,128] = wf[N,960] @ W[960,128] + bias
// (unchanged from round 4 — validated)
// ---------------------------------------------------------------------------
#define ROWB  80
#define TILEB (128 * ROWB)
#define BUFB  (4 * TILEB)
#define SMEM_GEMM (2 * BUFB + 512)

__global__ __launch_bounds__(256) void kpconv_gemm_mma(
    const float* __restrict__ bias, float* __restrict__ out)
{
    extern __shared__ char sm[];
    const int t    = threadIdx.x;
    const int lane = t & 31;
    const int wid  = t >> 5;
    const int wm   = (wid >> 2) * 64;
    const int wn   = (wid & 3) * 32;
    const int bm   = blockIdx.x * 128;

    float* sbias = reinterpret_cast<float*>(sm + 2 * BUFB);
    if (t < COUTV) sbias[t] = bias[t];

    const uint32_t smb = (uint32_t)__cvta_generic_to_shared(sm);

    const uint4* gAh = reinterpret_cast<const uint4*>(g_wfh);
    const uint4* gAl = reinterpret_cast<const uint4*>(g_wfl);
    const uint4* gBh = reinterpret_cast<const uint4*>(g_wth);
    const uint4* gBl = reinterpret_cast<const uint4*>(g_wtl);

    const int r0 = t >> 2, s0 = t & 3;
    const int r1 = (t + 256) >> 2, s1 = t & 3;

    float acc[4][4][4];
#pragma unroll
    for (int mi = 0; mi < 4; mi++)
#pragma unroll
        for (int ni = 0; ni < 4; ni++)
#pragma unroll
            for (int e = 0; e < 4; e++) acc[mi][ni][e] = 0.0f;

    const int a_r = lane & 15, a_c = lane >> 4;
    const int b_r = lane & 7,  b_c = (lane >> 3) & 1;

    auto prefetch = [&](int it, int buf) {
        const uint32_t base = smb + buf * BUFB;
#pragma unroll
        for (int j = 0; j < 2; j++) {
            const int row = j ? r1 : r0;
            const int seg = j ? s1 : s0;
            const uint32_t d = base + row * ROWB + seg * 16;
            const size_t ga = (size_t)(bm + row) * (KD / 8) + it * 4 + seg;
            const size_t gb = (size_t)row * (KD / 8) + it * 4 + seg;
            cp16(d + 0 * TILEB, gAh + ga);
            cp16(d + 1 * TILEB, gAl + ga);
            cp16(d + 2 * TILEB, gBh + gb);
            cp16(d + 3 * TILEB, gBl + gb);
        }
        asm volatile("cp.async.commit_group;" ::: "memory");
    };

    prefetch(0, 0);

    for (int it = 0; it < NITER; it++) {
        const int buf = it & 1;
        if (it + 1 < NITER) {
            prefetch(it + 1, buf ^ 1);
            asm volatile("cp.async.wait_group 1;" ::: "memory");
        } else {
            asm volatile("cp.async.wait_group 0;" ::: "memory");
        }
        __syncthreads();

        const uint32_t base = smb + buf * BUFB;
#pragma unroll
        for (int ks = 0; ks < 2; ks++) {
            uint32_t ah[4][4], al[4][4], bh[4][2], bl[4][2];
#pragma unroll
            for (int mi = 0; mi < 4; mi++) {
                const uint32_t ao = base + (wm + mi * 16 + a_r) * ROWB + ks * 32 + a_c * 16;
                ldsm4(ah[mi], ao);
                ldsm4(al[mi], ao + TILEB);
            }
#pragma unroll
            for (int ni = 0; ni < 4; ni++) {
                const uint32_t bo = base + 2 * TILEB +
                                    (wn + ni * 8 + b_r) * ROWB + ks * 32 + b_c * 16;
                ldsm2(bh[ni], bo);
                ldsm2(bl[ni], bo + TILEB);
            }
#pragma unroll
            for (int mi = 0; mi < 4; mi++)
#pragma unroll
                for (int ni = 0; ni < 4; ni++) {
                    mma16816(acc[mi][ni], ah[mi], bh[ni]);
                    mma16816(acc[mi][ni], ah[mi], bl[ni]);
                    mma16816(acc[mi][ni], al[mi], bh[ni]);
                }
        }
        __syncthreads();
    }

    const int er = lane >> 2;
    const int ec = (lane & 3) * 2;
#pragma unroll
    for (int mi = 0; mi < 4; mi++) {
#pragma unroll
        for (int half = 0; half < 2; half++) {
            const int gm = bm + wm + mi * 16 + er + half * 8;
            if (gm < NQ) {
#pragma unroll
                for (int ni = 0; ni < 4; ni++) {
                    const int n = wn + ni * 8 + ec;
                    float2 v;
                    v.x = acc[mi][ni][half * 2 + 0] + sbias[n + 0];
                    v.y = acc[mi][ni][half * 2 + 1] + sbias[n + 1];
                    *reinterpret_cast<float2*>(out + (size_t)gm * COUTV + n) = v;
                }
            }
        }
    }
}

// ---------------------------------------------------------------------------
extern "C" void kernel_launch(void* const* d_in, const int* in_sizes, int n_in,
                              void* d_out, int out_size)
{
    const float* q    = (const float*)d_in[0];      // [N,3]
    const float* s    = (const float*)d_in[1];      // [M,3]
    const int*   nb   = (const int*)d_in[2];        // [N,H] int32
    const float* x    = (const float*)d_in[3];      // [M,64]
    const float* kp   = (const float*)d_in[4];      // [15,3]
    const float* w    = (const float*)d_in[5];      // [15,64,128]
    const float* bias = (const float*)d_in[6];      // [128]
    float*       out  = (float*)d_out;              // [N,128]

    cudaFuncSetAttribute(kpconv_gather_mma,
                         cudaFuncAttributeMaxDynamicSharedMemorySize, GSMEM);
    cudaFuncSetAttribute(kpconv_gemm_mma,
                         cudaFuncAttributeMaxDynamicSharedMemorySize, SMEM_GEMM);

    kp_prep<<<512, 256>>>(w);
    kp_prep_x<<<(MS * CINV) / 256, 256>>>(x);
    kpconv_gather_mma<<<NQ / 8, 256, GSMEM>>>(q, s, nb, kp);
    kpconv_gemm_mma<<<NPAD / 128, 256, SMEM_GEMM>>>(bias, out);
}

// round 6
// speedup vs baseline: 1.2811x; 1.2811x over previous
#include <cuda_runtime.h>
#include <cuda_bf16.h>
#include <cstdint>

// Problem constants
#define NQ    50000
#define MS    50000
#define HN    32
#define KKP   15
#define KP16  16
#define CINV  64
#define COUTV 128
#define KD    1024          // scratch row length (16 kp x 64 cin); >=960 is zero pad
#define KREAL 960
#define NPAD  50048         // 782 * 64
#define NITER 30            // 960 / 32

// ---------------------------------------------------------------------------
// Scratch (device globals; zero-initialized at load -> padding stays zero)
// ---------------------------------------------------------------------------
__device__ __nv_bfloat16 g_wfh[(size_t)NPAD * KD];   // wf hi  [n][kd]
__device__ __nv_bfloat16 g_wfl[(size_t)NPAD * KD];   // wf lo
__device__ __nv_bfloat16 g_wth[(size_t)COUTV * KD];  // W^T hi [cout][kd]
__device__ __nv_bfloat16 g_wtl[(size_t)COUTV * KD];  // W^T lo

// ---------------------------------------------------------------------------
// helpers (baseline PTX features only; f32x2 is sm_100+ non-'a')
// ---------------------------------------------------------------------------
__device__ __forceinline__ void ldsm4(uint32_t* r, uint32_t a) {
    asm volatile("ldmatrix.sync.aligned.m8n8.x4.shared.b16 {%0,%1,%2,%3}, [%4];"
                 : "=r"(r[0]), "=r"(r[1]), "=r"(r[2]), "=r"(r[3]) : "r"(a));
}
__device__ __forceinline__ void ldsm2(uint32_t* r, uint32_t a) {
    asm volatile("ldmatrix.sync.aligned.m8n8.x2.shared.b16 {%0,%1}, [%2];"
                 : "=r"(r[0]), "=r"(r[1]) : "r"(a));
}
__device__ __forceinline__ void mma16816(float* c, const uint32_t* a, const uint32_t* b) {
    asm volatile(
        "mma.sync.aligned.m16n8k16.row.col.f32.bf16.bf16.f32 "
        "{%0,%1,%2,%3}, {%4,%5,%6,%7}, {%8,%9}, {%0,%1,%2,%3};"
        : "+f"(c[0]), "+f"(c[1]), "+f"(c[2]), "+f"(c[3])
        : "r"(a[0]), "r"(a[1]), "r"(a[2]), "r"(a[3]), "r"(b[0]), "r"(b[1]));
}
__device__ __forceinline__ void cp16(uint32_t saddr, const void* gaddr) {
    asm volatile("cp.async.cg.shared.global [%0], [%1], 16;"
                 :: "r"(saddr), "l"(gaddr) : "memory");
}
__device__ __forceinline__ unsigned long long fma2(unsigned long long a,
                                                   unsigned long long b,
                                                   unsigned long long c) {
    unsigned long long d;
    asm("fma.rn.f32x2 %0, %1, %2, %3;" : "=l"(d) : "l"(a), "l"(b), "l"(c));
    return d;
}
__device__ __forceinline__ unsigned long long pack2(float lo, float hi) {
    unsigned long long d;
    asm("mov.b64 %0, {%1, %2};" : "=l"(d) : "f"(lo), "f"(hi));
    return d;
}
__device__ __forceinline__ void unpack2(unsigned long long v, float& lo, float& hi) {
    asm("mov.b64 {%0, %1}, %2;" : "=f"(lo), "=f"(hi) : "l"(v));
}

// ---------------------------------------------------------------------------
// Kernel 0: weights -> W^T, bf16 hi/lo split.  Wt[cout][kd] = W[kd][cout]
// ---------------------------------------------------------------------------
__global__ __launch_bounds__(256) void kp_prep(const float* __restrict__ W) {
    const int id = blockIdx.x * 256 + threadIdx.x;       // 0 .. 131071
    const int kd = id & (KD - 1);
    const int n  = id >> 10;
    float v = (kd < KREAL) ? W[kd * COUTV + n] : 0.0f;
    __nv_bfloat16 h = __float2bfloat16_rn(v);
    __nv_bfloat16 l = __float2bfloat16_rn(v - __bfloat162float(h));
    g_wth[id] = h;
    g_wtl[id] = l;
}

// ---------------------------------------------------------------------------
// Kernel 1: gather + influence weights + H-reduction (f32x2 packed FMA).
// Block = 128 threads = 8 queries x 16 c4-groups.
// Thread owns 8 k-pairs x 4 channels, accumulated as packed f32x2.
// ---------------------------------------------------------------------------
__global__ __launch_bounds__(128) void kpconv_gather(
    const float* __restrict__ q,
    const float* __restrict__ s,
    const int* __restrict__ nb,
    const float* __restrict__ x,
    const float* __restrict__ kp)
{
    __shared__ int   idxs[8][HN];
    __shared__ float wk[8][HN][KP16];
    __shared__ float kps[48];

    const int t  = threadIdx.x;
    const int n0 = blockIdx.x * 8;
    const int tq = t >> 4;
    const int tc = t & 15;
    const int n  = n0 + tq;

    if (t < KKP * 3) kps[t] = kp[t];
#pragma unroll
    for (int i = t; i < 8 * HN; i += 128) {
        const int qq = i >> 5, h = i & 31;
        int j = nb[(size_t)(n0 + qq) * HN + h];
        j = j < 0 ? 0 : (j >= MS ? MS - 1 : j);
        idxs[qq][h] = j;
    }
    __syncthreads();

    // influence weights: thread covers h = tc and tc+16 for its query
    {
        const float qx = q[n * 3 + 0];
        const float qy = q[n * 3 + 1];
        const float qz = q[n * 3 + 2];
#pragma unroll
        for (int hh = 0; hh < 2; hh++) {
            const int h = tc + hh * 16;
            const int j = idxs[tq][h];
            const float nx = s[j * 3 + 0] - qx;
            const float ny = s[j * 3 + 1] - qy;
            const float nz = s[j * 3 + 2] - qz;
#pragma unroll
            for (int k = 0; k < KKP; k++) {
                const float dx = nx - kps[k * 3 + 0];
                const float dy = ny - kps[k * 3 + 1];
                const float dz = nz - kps[k * 3 + 2];
                const float d2 = dx * dx + dy * dy + dz * dz;
                const float w  = 1.0f - sqrtf(d2) * (1.0f / 0.072f);
                wk[tq][h][k] = w > 0.0f ? w : 0.0f;
            }
            wk[tq][h][15] = 0.0f;
        }
    }
    __syncthreads();

    // H-reduction: acc[kpair][channel] packed (k even in .lo, k odd in .hi)
    unsigned long long acc[8][4];
#pragma unroll
    for (int p = 0; p < 8; p++)
#pragma unroll
        for (int c = 0; c < 4; c++) acc[p][c] = 0ull;

    const float4* x4 = reinterpret_cast<const float4*>(x);
#pragma unroll 2
    for (int h = 0; h < HN; h++) {
        const int j = idxs[tq][h];
        const float4 xv = x4[(size_t)j * (CINV / 4) + tc];
        unsigned long long xcc[4];
        xcc[0] = pack2(xv.x, xv.x);
        xcc[1] = pack2(xv.y, xv.y);
        xcc[2] = pack2(xv.z, xv.z);
        xcc[3] = pack2(xv.w, xv.w);
        const ulonglong2* wp = reinterpret_cast<const ulonglong2*>(&wk[tq][h][0]);
        unsigned long long wpair[8];
#pragma unroll
        for (int g = 0; g < 4; g++) {
            const ulonglong2 v = wp[g];
            wpair[2 * g + 0] = v.x;
            wpair[2 * g + 1] = v.y;
        }
#pragma unroll
        for (int p = 0; p < 8; p++)
#pragma unroll
            for (int c = 0; c < 4; c++)
                acc[p][c] = fma2(wpair[p], xcc[c], acc[p][c]);
    }

    // store bf16 hi/lo (uint2 = 4 bf16 each); skip k=15 (stays zero)
    uint2* outh = reinterpret_cast<uint2*>(g_wfh);
    uint2* outl = reinterpret_cast<uint2*>(g_wfl);
#pragma unroll
    for (int k = 0; k < KKP; k++) {
        float a[4];
#pragma unroll
        for (int c = 0; c < 4; c++) {
            float lo, hi;
            unpack2(acc[k >> 1][c], lo, hi);
            a[c] = (k & 1) ? hi : lo;
        }
        __nv_bfloat16 hb[4], lb[4];
#pragma unroll
        for (int u = 0; u < 4; u++) {
            hb[u] = __float2bfloat16_rn(a[u]);
            lb[u] = __float2bfloat16_rn(a[u] - __bfloat162float(hb[u]));
        }
        __nv_bfloat162 h01, h23, l01, l23;
        h01.x = hb[0]; h01.y = hb[1]; h23.x = hb[2]; h23.y = hb[3];
        l01.x = lb[0]; l01.y = lb[1]; l23.x = lb[2]; l23.y = lb[3];
        const size_t o = (size_t)n * (KD / 4) + k * 16 + tc;
        outh[o] = make_uint2(*reinterpret_cast<uint32_t*>(&h01),
                             *reinterpret_cast<uint32_t*>(&h23));
        outl[o] = make_uint2(*reinterpret_cast<uint32_t*>(&l01),
                             *reinterpret_cast<uint32_t*>(&l23));
    }
}

// ---------------------------------------------------------------------------
// Kernel 2: bf16 mma.sync GEMM  out[N,128] = wf[N,960] @ W[960,128] + bias
// Block tile 64x128, 8 warps (32x32 warp tiles), BK=32, cp.async double buffer,
// streamed fragments (no spills), 3 blocks/SM.
// ---------------------------------------------------------------------------
#define ROWB   80                  // 64B row + 16B pad
#define OFF_AH 0
#define OFF_AL (64 * ROWB)         // 5120
#define OFF_BH (2 * 64 * ROWB)     // 10240
#define OFF_BL (OFF_BH + 128 * ROWB)
#define BUFB   (OFF_BL + 128 * ROWB)   // 30720
#define SMEM_GEMM (2 * BUFB + 512)

__global__ __launch_bounds__(256, 3) void kpconv_gemm_mma(
    const float* __restrict__ bias, float* __restrict__ out)
{
    extern __shared__ char sm[];
    const int t    = threadIdx.x;
    const int lane = t & 31;
    const int wid  = t >> 5;
    const int wm   = (wid >> 2) * 32;   // 0 or 32
    const int wn   = (wid & 3) * 32;    // 0,32,64,96
    const int bm   = blockIdx.x * 64;

    float* sbias = reinterpret_cast<float*>(sm + 2 * BUFB);
    if (t < COUTV) sbias[t] = bias[t];

    const uint32_t smb = (uint32_t)__cvta_generic_to_shared(sm);

    const uint4* gAh = reinterpret_cast<const uint4*>(g_wfh);
    const uint4* gAl = reinterpret_cast<const uint4*>(g_wfl);
    const uint4* gBh = reinterpret_cast<const uint4*>(g_wth);
    const uint4* gBl = reinterpret_cast<const uint4*>(g_wtl);

    float acc[2][4][4];
#pragma unroll
    for (int mi = 0; mi < 2; mi++)
#pragma unroll
        for (int ni = 0; ni < 4; ni++)
#pragma unroll
            for (int e = 0; e < 4; e++) acc[mi][ni][e] = 0.0f;

    const int a_r = lane & 15, a_c = lane >> 4;
    const int b_r = lane & 7,  b_c = (lane >> 3) & 1;
    const int lrow = t >> 2, lseg = t & 3;

    auto prefetch = [&](int it, int buf) {
        const uint32_t base = smb + buf * BUFB;
        // A: 64 rows x 4 segs = 256 slots (1 per thread), hi+lo
        {
            const size_t ga = (size_t)(bm + lrow) * (KD / 8) + it * 4 + lseg;
            const uint32_t da = base + lrow * ROWB + lseg * 16;
            cp16(da + OFF_AH, gAh + ga);
            cp16(da + OFF_AL, gAl + ga);
        }
        // B: 128 rows x 4 segs = 512 slots (2 per thread), hi+lo
#pragma unroll
        for (int jj = 0; jj < 2; jj++) {
            const int rb = lrow + jj * 64;
            const size_t gb = (size_t)rb * (KD / 8) + it * 4 + lseg;
            const uint32_t db = base + OFF_BH + rb * ROWB + lseg * 16;
            cp16(db, gBh + gb);
            cp16(db + (OFF_BL - OFF_BH), gBl + gb);
        }
        asm volatile("cp.async.commit_group;" ::: "memory");
    };

    prefetch(0, 0);

    for (int it = 0; it < NITER; it++) {
        const int buf = it & 1;
        if (it + 1 < NITER) {
            prefetch(it + 1, buf ^ 1);
            asm volatile("cp.async.wait_group 1;" ::: "memory");
        } else {
            asm volatile("cp.async.wait_group 0;" ::: "memory");
        }
        __syncthreads();

        const uint32_t base = smb + buf * BUFB;
#pragma unroll
        for (int ks = 0; ks < 2; ks++) {
            uint32_t af[2][4], bh[4][2], bl[4][2];
            // load A-hi + B-hi/lo; 2 products; then reload A-lo into af; 3rd.
#pragma unroll
            for (int mi = 0; mi < 2; mi++) {
                const uint32_t ao = base + OFF_AH +
                    (wm + mi * 16 + a_r) * ROWB + ks * 32 + a_c * 16;
                ldsm4(af[mi], ao);
            }
#pragma unroll
            for (int ni = 0; ni < 4; ni++) {
                const uint32_t bo = base + OFF_BH +
                    (wn + ni * 8 + b_r) * ROWB + ks * 32 + b_c * 16;
                ldsm2(bh[ni], bo);
                ldsm2(bl[ni], bo + (OFF_BL - OFF_BH));
            }
#pragma unroll
            for (int mi = 0; mi < 2; mi++)
#pragma unroll
                for (int ni = 0; ni < 4; ni++) {
                    mma16816(acc[mi][ni], af[mi], bh[ni]);
                    mma16816(acc[mi][ni], af[mi], bl[ni]);
                }
#pragma unroll
            for (int mi = 0; mi < 2; mi++) {
                const uint32_t ao = base + OFF_AL +
                    (wm + mi * 16 + a_r) * ROWB + ks * 32 + a_c * 16;
                ldsm4(af[mi], ao);
            }
#pragma unroll
            for (int mi = 0; mi < 2; mi++)
#pragma unroll
                for (int ni = 0; ni < 4; ni++)
                    mma16816(acc[mi][ni], af[mi], bh[ni]);
        }
        __syncthreads();
    }

    const int er = lane >> 2;
    const int ec = (lane & 3) * 2;
#pragma unroll
    for (int mi = 0; mi < 2; mi++) {
#pragma unroll
        for (int half = 0; half < 2; half++) {
            const int gm = bm + wm + mi * 16 + er + half * 8;
            if (gm < NQ) {
#pragma unroll
                for (int ni = 0; ni < 4; ni++) {
                    const int nn = wn + ni * 8 + ec;
                    float2 v;
                    v.x = acc[mi][ni][half * 2 + 0] + sbias[nn + 0];
                    v.y = acc[mi][ni][half * 2 + 1] + sbias[nn + 1];
                    *reinterpret_cast<float2*>(out + (size_t)gm * COUTV + nn) = v;
                }
            }
        }
    }
}

// ---------------------------------------------------------------------------
extern "C" void kernel_launch(void* const* d_in, const int* in_sizes, int n_in,
                              void* d_out, int out_size)
{
    const float* q    = (const float*)d_in[0];      // [N,3]
    const float* s    = (const float*)d_in[1];      // [M,3]
    const int*   nb   = (const int*)d_in[2];        // [N,H] int32
    const float* x    = (const float*)d_in[3];      // [M,64]
    const float* kp   = (const float*)d_in[4];      // [15,3]
    const float* w    = (const float*)d_in[5];      // [15,64,128]
    const float* bias = (const float*)d_in[6];      // [128]
    float*       out  = (float*)d_out;              // [N,128]

    cudaFuncSetAttribute(kpconv_gemm_mma,
                         cudaFuncAttributeMaxDynamicSharedMemorySize, SMEM_GEMM);

    kp_prep<<<512, 256>>>(w);
    kpconv_gather<<<NQ / 8, 128>>>(q, s, nb, x, kp);
    kpconv_gemm_mma<<<NPAD / 64, 256, SMEM_GEMM>>>(bias, out);
}

// round 7
// speedup vs baseline: 1.3739x; 1.0725x over previous
#include <cuda_runtime.h>
#include <cuda_bf16.h>
#include <cstdint>

// Problem constants
#define NQ    50000
#define MS    50000
#define HN    32
#define KKP   15
#define KP16  16
#define CINV  64
#define COUTV 128
#define KD    1024          // scratch row length (16 kp x 64 cin); >=960 is zero pad
#define KREAL 960
#define NPAD  50048         // 391 * 128
#define NITER 30            // 960 / 32

// ---------------------------------------------------------------------------
// Scratch (device globals; zero-initialized at load -> padding stays zero)
// ---------------------------------------------------------------------------
__device__ __nv_bfloat16 g_wfh[(size_t)NPAD * KD];   // wf hi  [n][kd]
__device__ __nv_bfloat16 g_wfl[(size_t)NPAD * KD];   // wf lo
__device__ __nv_bfloat16 g_wth[(size_t)COUTV * KD];  // W^T hi [cout][kd]
__device__ __nv_bfloat16 g_wtl[(size_t)COUTV * KD];  // W^T lo

// ---------------------------------------------------------------------------
// mma / ldmatrix / cp.async helpers (baseline PTX features only)
// ---------------------------------------------------------------------------
__device__ __forceinline__ void ldsm4(uint32_t* r, uint32_t a) {
    asm volatile("ldmatrix.sync.aligned.m8n8.x4.shared.b16 {%0,%1,%2,%3}, [%4];"
                 : "=r"(r[0]), "=r"(r[1]), "=r"(r[2]), "=r"(r[3]) : "r"(a));
}
__device__ __forceinline__ void ldsm2(uint32_t* r, uint32_t a) {
    asm volatile("ldmatrix.sync.aligned.m8n8.x2.shared.b16 {%0,%1}, [%2];"
                 : "=r"(r[0]), "=r"(r[1]) : "r"(a));
}
__device__ __forceinline__ void mma16816(float* c, const uint32_t* a, const uint32_t* b) {
    asm volatile(
        "mma.sync.aligned.m16n8k16.row.col.f32.bf16.bf16.f32 "
        "{%0,%1,%2,%3}, {%4,%5,%6,%7}, {%8,%9}, {%0,%1,%2,%3};"
        : "+f"(c[0]), "+f"(c[1]), "+f"(c[2]), "+f"(c[3])
        : "r"(a[0]), "r"(a[1]), "r"(a[2]), "r"(a[3]), "r"(b[0]), "r"(b[1]));
}
__device__ __forceinline__ void cp16(uint32_t saddr, const void* gaddr) {
    asm volatile("cp.async.cg.shared.global [%0], [%1], 16;"
                 :: "r"(saddr), "l"(gaddr) : "memory");
}

// ---------------------------------------------------------------------------
// Kernel 1: gather + influence weights + H-reduction -> bf16 hi/lo scratch.
// Block = 128 threads = 8 queries x 16 c4-groups. Thread owns 16 k-accumulators.
// Blocks 0..1023 additionally prep W^T hi/lo (folded former kp_prep kernel).
// ---------------------------------------------------------------------------
__global__ __launch_bounds__(128) void kpconv_gather(
    const float* __restrict__ q,
    const float* __restrict__ s,
    const int* __restrict__ nb,
    const float* __restrict__ x,
    const float* __restrict__ kp,
    const float* __restrict__ W)
{
    __shared__ int   idxs[8][HN];
    __shared__ float wk[8][HN][KP16];
    __shared__ float kps[48];

    const int t  = threadIdx.x;
    const int n0 = blockIdx.x * 8;
    const int tq = t >> 4;
    const int tc = t & 15;
    const int n  = n0 + tq;

    // folded weight prep: blocks 0..1023 cover 131072 W^T elements
    if (blockIdx.x < 1024) {
        const int id = blockIdx.x * 128 + t;             // 0 .. 131071
        const int kd = id & (KD - 1);
        const int cо = id >> 10;
        float v = (kd < KREAL) ? W[kd * COUTV + cо] : 0.0f;
        __nv_bfloat16 h = __float2bfloat16_rn(v);
        __nv_bfloat16 l = __float2bfloat16_rn(v - __bfloat162float(h));
        g_wth[id] = h;
        g_wtl[id] = l;
    }

    if (t < KKP * 3) kps[t] = kp[t];
#pragma unroll
    for (int i = t; i < 8 * HN; i += 128) {
        const int qq = i >> 5, h = i & 31;
        int j = nb[(size_t)(n0 + qq) * HN + h];
        j = j < 0 ? 0 : (j >= MS ? MS - 1 : j);
        idxs[qq][h] = j;
    }
    __syncthreads();

    // influence weights: thread covers h = tc and tc+16 for its query
    {
        const float qx = q[n * 3 + 0];
        const float qy = q[n * 3 + 1];
        const float qz = q[n * 3 + 2];
#pragma unroll
        for (int hh = 0; hh < 2; hh++) {
            const int h = tc + hh * 16;
            const int j = idxs[tq][h];
            const float nx = s[j * 3 + 0] - qx;
            const float ny = s[j * 3 + 1] - qy;
            const float nz = s[j * 3 + 2] - qz;
#pragma unroll
            for (int k = 0; k < KKP; k++) {
                const float dx = nx - kps[k * 3 + 0];
                const float dy = ny - kps[k * 3 + 1];
                const float dz = nz - kps[k * 3 + 2];
                const float d2 = dx * dx + dy * dy + dz * dz;
                const float w  = 1.0f - sqrtf(d2) * (1.0f / 0.072f);
                wk[tq][h][k] = w > 0.0f ? w : 0.0f;
            }
            wk[tq][h][15] = 0.0f;
        }
    }
    __syncthreads();

    // H-reduction: acc[k] (float4 over cin group) for all k
    float4 acc[KP16];
#pragma unroll
    for (int k = 0; k < KP16; k++) acc[k] = make_float4(0.f, 0.f, 0.f, 0.f);

    const float4* x4 = reinterpret_cast<const float4*>(x);
#pragma unroll 4
    for (int h = 0; h < HN; h++) {
        const int j = idxs[tq][h];
        const float4 xv = x4[(size_t)j * (CINV / 4) + tc];
        const float4* wrow = reinterpret_cast<const float4*>(&wk[tq][h][0]);
        float wv[KP16];
#pragma unroll
        for (int g = 0; g < 4; g++) {
            const float4 wq = wrow[g];
            wv[g * 4 + 0] = wq.x; wv[g * 4 + 1] = wq.y;
            wv[g * 4 + 2] = wq.z; wv[g * 4 + 3] = wq.w;
        }
#pragma unroll
        for (int k = 0; k < KP16; k++) {
            const float w = wv[k];
            acc[k].x += w * xv.x; acc[k].y += w * xv.y;
            acc[k].z += w * xv.z; acc[k].w += w * xv.w;
        }
    }

    // store bf16 hi/lo (uint2 = 4 bf16 each); skip k=15 (stays zero)
    uint2* outh = reinterpret_cast<uint2*>(g_wfh);
    uint2* outl = reinterpret_cast<uint2*>(g_wfl);
#pragma unroll
    for (int k = 0; k < KKP; k++) {
        float a[4] = {acc[k].x, acc[k].y, acc[k].z, acc[k].w};
        __nv_bfloat16 hb[4], lb[4];
#pragma unroll
        for (int u = 0; u < 4; u++) {
            hb[u] = __float2bfloat16_rn(a[u]);
            lb[u] = __float2bfloat16_rn(a[u] - __bfloat162float(hb[u]));
        }
        __nv_bfloat162 h01, h23, l01, l23;
        h01.x = hb[0]; h01.y = hb[1]; h23.x = hb[2]; h23.y = hb[3];
        l01.x = lb[0]; l01.y = lb[1]; l23.x = lb[2]; l23.y = lb[3];
        const size_t o = (size_t)n * (KD / 4) + k * 16 + tc;
        outh[o] = make_uint2(*reinterpret_cast<uint32_t*>(&h01),
                             *reinterpret_cast<uint32_t*>(&h23));
        outl[o] = make_uint2(*reinterpret_cast<uint32_t*>(&l01),
                             *reinterpret_cast<uint32_t*>(&l23));
    }
}

// ---------------------------------------------------------------------------
// Kernel 2: bf16 mma.sync GEMM  out[N,128] = wf[N,960] @ W[960,128] + bias
// Block tile 128x128, 8 warps (64x32 warp tiles), BK=32, cp.async double buffer.
// STREAMED A fragments: ah used for 2 products, then same regs reloaded with al
// -> peak live regs ~115, no spills (round-4 version spilled at 127).
// ---------------------------------------------------------------------------
#define ROWB  80                 // smem bytes per 32-bf16 row (64B + 16B pad)
#define TILEB (128 * ROWB)       // 10240
#define BUFB  (4 * TILEB)        // Ah, Al, Bh, Bl
#define SMEM_GEMM (2 * BUFB + 512)

__global__ __launch_bounds__(256) void kpconv_gemm_mma(
    const float* __restrict__ bias, float* __restrict__ out)
{
    extern __shared__ char sm[];
    const int t    = threadIdx.x;
    const int lane = t & 31;
    const int wid  = t >> 5;
    const int wm   = (wid >> 2) * 64;   // 0 or 64
    const int wn   = (wid & 3) * 32;    // 0,32,64,96
    const int bm   = blockIdx.x * 128;

    float* sbias = reinterpret_cast<float*>(sm + 2 * BUFB);
    if (t < COUTV) sbias[t] = bias[t];

    const uint32_t smb = (uint32_t)__cvta_generic_to_shared(sm);

    const uint4* gAh = reinterpret_cast<const uint4*>(g_wfh);
    const uint4* gAl = reinterpret_cast<const uint4*>(g_wfl);
    const uint4* gBh = reinterpret_cast<const uint4*>(g_wth);
    const uint4* gBl = reinterpret_cast<const uint4*>(g_wtl);

    const int r0 = t >> 2, s0 = t & 3;
    const int r1 = (t + 256) >> 2, s1 = t & 3;

    float acc[4][4][4];
#pragma unroll
    for (int mi = 0; mi < 4; mi++)
#pragma unroll
        for (int ni = 0; ni < 4; ni++)
#pragma unroll
            for (int e = 0; e < 4; e++) acc[mi][ni][e] = 0.0f;

    const int a_r = lane & 15, a_c = lane >> 4;
    const int b_r = lane & 7,  b_c = (lane >> 3) & 1;

    auto prefetch = [&](int it, int buf) {
        const uint32_t base = smb + buf * BUFB;
#pragma unroll
        for (int j = 0; j < 2; j++) {
            const int row = j ? r1 : r0;
            const int seg = j ? s1 : s0;
            const uint32_t d = base + row * ROWB + seg * 16;
            const size_t ga = (size_t)(bm + row) * (KD / 8) + it * 4 + seg;
            const size_t gb = (size_t)row * (KD / 8) + it * 4 + seg;
            cp16(d + 0 * TILEB, gAh + ga);
            cp16(d + 1 * TILEB, gAl + ga);
            cp16(d + 2 * TILEB, gBh + gb);
            cp16(d + 3 * TILEB, gBl + gb);
        }
        asm volatile("cp.async.commit_group;" ::: "memory");
    };

    prefetch(0, 0);

    for (int it = 0; it < NITER; it++) {
        const int buf = it & 1;
        if (it + 1 < NITER) {
            prefetch(it + 1, buf ^ 1);
            asm volatile("cp.async.wait_group 1;" ::: "memory");
        } else {
            asm volatile("cp.async.wait_group 0;" ::: "memory");
        }
        __syncthreads();

        const uint32_t base = smb + buf * BUFB;
#pragma unroll
        for (int ks = 0; ks < 2; ks++) {
            uint32_t af[4][4], bh[4][2], bl[4][2];
            // Phase 1: A-hi fragments + B hi/lo fragments, 2 products each
#pragma unroll
            for (int mi = 0; mi < 4; mi++) {
                const uint32_t ao = base + (wm + mi * 16 + a_r) * ROWB + ks * 32 + a_c * 16;
                ldsm4(af[mi], ao);
            }
#pragma unroll
            for (int ni = 0; ni < 4; ni++) {
                const uint32_t bo = base + 2 * TILEB +
                                    (wn + ni * 8 + b_r) * ROWB + ks * 32 + b_c * 16;
                ldsm2(bh[ni], bo);
                ldsm2(bl[ni], bo + TILEB);
            }
#pragma unroll
            for (int mi = 0; mi < 4; mi++)
#pragma unroll
                for (int ni = 0; ni < 4; ni++) {
                    mma16816(acc[mi][ni], af[mi], bh[ni]);
                    mma16816(acc[mi][ni], af[mi], bl[ni]);
                }
            // Phase 2: reload same regs with A-lo, 3rd product
#pragma unroll
            for (int mi = 0; mi < 4; mi++) {
                const uint32_t ao = base + TILEB +
                                    (wm + mi * 16 + a_r) * ROWB + ks * 32 + a_c * 16;
                ldsm4(af[mi], ao);
            }
#pragma unroll
            for (int mi = 0; mi < 4; mi++)
#pragma unroll
                for (int ni = 0; ni < 4; ni++)
                    mma16816(acc[mi][ni], af[mi], bh[ni]);
        }
        __syncthreads();
    }

    const int er = lane >> 2;
    const int ec = (lane & 3) * 2;
#pragma unroll
    for (int mi = 0; mi < 4; mi++) {
#pragma unroll
        for (int half = 0; half < 2; half++) {
            const int gm = bm + wm + mi * 16 + er + half * 8;
            if (gm < NQ) {
#pragma unroll
                for (int ni = 0; ni < 4; ni++) {
                    const int n = wn + ni * 8 + ec;
                    float2 v;
                    v.x = acc[mi][ni][half * 2 + 0] + sbias[n + 0];
                    v.y = acc[mi][ni][half * 2 + 1] + sbias[n + 1];
                    *reinterpret_cast<float2*>(out + (size_t)gm * COUTV + n) = v;
                }
            }
        }
    }
}

// ---------------------------------------------------------------------------
extern "C" void kernel_launch(void* const* d_in, const int* in_sizes, int n_in,
                              void* d_out, int out_size)
{
    const float* q    = (const float*)d_in[0];      // [N,3]
    const float* s    = (const float*)d_in[1];      // [M,3]
    const int*   nb   = (const int*)d_in[2];        // [N,H] int32
    const float* x    = (const float*)d_in[3];      // [M,64]
    const float* kp   = (const float*)d_in[4];      // [15,3]
    const float* w    = (const float*)d_in[5];      // [15,64,128]
    const float* bias = (const float*)d_in[6];      // [128]
    float*       out  = (float*)d_out;              // [N,128]

    cudaFuncSetAttribute(kpconv_gemm_mma,
                         cudaFuncAttributeMaxDynamicSharedMemorySize, SMEM_GEMM);

    kpconv_gather<<<NQ / 8, 128>>>(q, s, nb, x, kp, w);
    kpconv_gemm_mma<<<NPAD / 128, 256, SMEM_GEMM>>>(bias, out);
}

// round 8
// speedup vs baseline: 1.6893x; 1.2295x over previous
#include <cuda_runtime.h>
#include <cuda_fp16.h>
#include <cstdint>

// Problem constants
#define NQ    50000
#define MS    50000
#define HN    32
#define KKP   15
#define KP16  16
#define CINV  64
#define COUTV 128
#define KD    1024          // scratch row length (16 kp x 64 cin); >=960 is zero pad
#define KREAL 960
#define NPAD  50048         // 391 * 128
#define NITER 30            // 960 / 32

// ---------------------------------------------------------------------------
// Scratch (device globals; zero-initialized at load -> padding stays zero)
// A = wf in single fp16; B = W^T in fp16 hi/lo (2-product split scheme).
// ---------------------------------------------------------------------------
__device__ __half g_wf[(size_t)NPAD * KD];           // wf  [n][kd] fp16
__device__ __half g_wth[(size_t)COUTV * KD];         // W^T hi [cout][kd]
__device__ __half g_wtl[(size_t)COUTV * KD];         // W^T lo

// ---------------------------------------------------------------------------
// mma / ldmatrix / cp.async helpers (baseline PTX features only)
// ---------------------------------------------------------------------------
__device__ __forceinline__ void ldsm4(uint32_t* r, uint32_t a) {
    asm volatile("ldmatrix.sync.aligned.m8n8.x4.shared.b16 {%0,%1,%2,%3}, [%4];"
                 : "=r"(r[0]), "=r"(r[1]), "=r"(r[2]), "=r"(r[3]) : "r"(a));
}
__device__ __forceinline__ void mma16816h(float* c, const uint32_t* a, const uint32_t* b) {
    asm volatile(
        "mma.sync.aligned.m16n8k16.row.col.f32.f16.f16.f32 "
        "{%0,%1,%2,%3}, {%4,%5,%6,%7}, {%8,%9}, {%0,%1,%2,%3};"
        : "+f"(c[0]), "+f"(c[1]), "+f"(c[2]), "+f"(c[3])
        : "r"(a[0]), "r"(a[1]), "r"(a[2]), "r"(a[3]), "r"(b[0]), "r"(b[1]));
}
__device__ __forceinline__ void cp16(uint32_t saddr, const void* gaddr) {
    asm volatile("cp.async.cg.shared.global [%0], [%1], 16;"
                 :: "r"(saddr), "l"(gaddr) : "memory");
}

// ---------------------------------------------------------------------------
// Kernel 1: gather + influence weights + H-reduction -> fp16 scratch.
// Block = 128 threads = 8 queries x 16 c4-groups. Thread owns 16 k-accumulators.
// Blocks 0..1023 additionally prep W^T fp16 hi/lo (folded weight prep).
// ---------------------------------------------------------------------------
__global__ __launch_bounds__(128) void kpconv_gather(
    const float* __restrict__ q,
    const float* __restrict__ s,
    const int* __restrict__ nb,
    const float* __restrict__ x,
    const float* __restrict__ kp,
    const float* __restrict__ W)
{
    __shared__ int   idxs[8][HN];
    __shared__ float wk[8][HN][KP16];
    __shared__ float kps[48];

    const int t  = threadIdx.x;
    const int n0 = blockIdx.x * 8;
    const int tq = t >> 4;
    const int tc = t & 15;
    const int n  = n0 + tq;

    // folded weight prep: blocks 0..1023 cover 131072 W^T elements
    if (blockIdx.x < 1024) {
        const int id = blockIdx.x * 128 + t;             // 0 .. 131071
        const int kd = id & (KD - 1);
        const int co = id >> 10;
        float v = (kd < KREAL) ? W[kd * COUTV + co] : 0.0f;
        __half h = __float2half_rn(v);
        __half l = __float2half_rn(v - __half2float(h));
        g_wth[id] = h;
        g_wtl[id] = l;
    }

    if (t < KKP * 3) kps[t] = kp[t];
#pragma unroll
    for (int i = t; i < 8 * HN; i += 128) {
        const int qq = i >> 5, h = i & 31;
        int j = nb[(size_t)(n0 + qq) * HN + h];
        j = j < 0 ? 0 : (j >= MS ? MS - 1 : j);
        idxs[qq][h] = j;
    }
    __syncthreads();

    // influence weights: thread covers h = tc and tc+16 for its query
    {
        const float qx = q[n * 3 + 0];
        const float qy = q[n * 3 + 1];
        const float qz = q[n * 3 + 2];
#pragma unroll
        for (int hh = 0; hh < 2; hh++) {
            const int h = tc + hh * 16;
            const int j = idxs[tq][h];
            const float nx = s[j * 3 + 0] - qx;
            const float ny = s[j * 3 + 1] - qy;
            const float nz = s[j * 3 + 2] - qz;
#pragma unroll
            for (int k = 0; k < KKP; k++) {
                const float dx = nx - kps[k * 3 + 0];
                const float dy = ny - kps[k * 3 + 1];
                const float dz = nz - kps[k * 3 + 2];
                const float d2 = dx * dx + dy * dy + dz * dz;
                const float w  = 1.0f - sqrtf(d2) * (1.0f / 0.072f);
                wk[tq][h][k] = w > 0.0f ? w : 0.0f;
            }
            wk[tq][h][15] = 0.0f;
        }
    }
    __syncthreads();

    // H-reduction: acc[k] (float4 over cin group) for all k
    float4 acc[KP16];
#pragma unroll
    for (int k = 0; k < KP16; k++) acc[k] = make_float4(0.f, 0.f, 0.f, 0.f);

    const float4* x4 = reinterpret_cast<const float4*>(x);
#pragma unroll 4
    for (int h = 0; h < HN; h++) {
        const int j = idxs[tq][h];
        const float4 xv = x4[(size_t)j * (CINV / 4) + tc];
        const float4* wrow = reinterpret_cast<const float4*>(&wk[tq][h][0]);
        float wv[KP16];
#pragma unroll
        for (int g = 0; g < 4; g++) {
            const float4 wq = wrow[g];
            wv[g * 4 + 0] = wq.x; wv[g * 4 + 1] = wq.y;
            wv[g * 4 + 2] = wq.z; wv[g * 4 + 3] = wq.w;
        }
#pragma unroll
        for (int k = 0; k < KP16; k++) {
            const float w = wv[k];
            acc[k].x += w * xv.x; acc[k].y += w * xv.y;
            acc[k].z += w * xv.z; acc[k].w += w * xv.w;
        }
    }

    // store fp16 (uint2 = 4 halves); skip k=15 (stays zero)
    uint2* outv = reinterpret_cast<uint2*>(g_wf);
#pragma unroll
    for (int k = 0; k < KKP; k++) {
        __half2 p01 = __floats2half2_rn(acc[k].x, acc[k].y);
        __half2 p23 = __floats2half2_rn(acc[k].z, acc[k].w);
        const size_t o = (size_t)n * (KD / 4) + k * 16 + tc;
        outv[o] = make_uint2(*reinterpret_cast<uint32_t*>(&p01),
                             *reinterpret_cast<uint32_t*>(&p23));
    }
}

// ---------------------------------------------------------------------------
// Kernel 2: fp16 mma.sync GEMM  out[N,128] = wf[N,960] @ W[960,128] + bias
// Block tile 128x128, 8 warps (64x32 warp tiles), BK=32, cp.async double buffer.
// 2 products per k16: A*Bh + A*Bl (A single fp16, B split fp16 hi/lo).
// 64 mma/iter (was 96) -> mma.sync issue roofline ~81us.
// ---------------------------------------------------------------------------
#define ROWB  80                 // smem bytes per 32-half row (64B + 16B pad)
#define TILEB (128 * ROWB)       // 10240
#define OFF_A  0
#define OFF_BH TILEB
#define OFF_BL (2 * TILEB)
#define BUFB  (3 * TILEB)        // A, Bh, Bl
#define SMEM_GEMM (2 * BUFB + 512)

__global__ __launch_bounds__(256) void kpconv_gemm_mma(
    const float* __restrict__ bias, float* __restrict__ out)
{
    extern __shared__ char sm[];
    const int t    = threadIdx.x;
    const int lane = t & 31;
    const int wid  = t >> 5;
    const int wm   = (wid >> 2) * 64;   // 0 or 64
    const int wn   = (wid & 3) * 32;    // 0,32,64,96
    const int bm   = blockIdx.x * 128;

    float* sbias = reinterpret_cast<float*>(sm + 2 * BUFB);
    if (t < COUTV) sbias[t] = bias[t];

    const uint32_t smb = (uint32_t)__cvta_generic_to_shared(sm);

    const uint4* gA  = reinterpret_cast<const uint4*>(g_wf);
    const uint4* gBh = reinterpret_cast<const uint4*>(g_wth);
    const uint4* gBl = reinterpret_cast<const uint4*>(g_wtl);

    float acc[4][4][4];
#pragma unroll
    for (int mi = 0; mi < 4; mi++)
#pragma unroll
        for (int ni = 0; ni < 4; ni++)
#pragma unroll
            for (int e = 0; e < 4; e++) acc[mi][ni][e] = 0.0f;

    // ldmatrix lane address components
    const int a_r  = lane & 15, a_c = lane >> 4;                // A x4
    const int b_r4 = ((lane >> 4) & 1) * 8 + (lane & 7);        // B x4 (2 ni tiles)
    const int b_c4 = (lane >> 3) & 1;

    auto prefetch = [&](int it, int buf) {
        const uint32_t base = smb + buf * BUFB;
#pragma unroll
        for (int j = 0; j < 2; j++) {
            const int row = (t + j * 256) >> 2;
            const int seg = t & 3;
            const uint32_t d = base + row * ROWB + seg * 16;
            const size_t ga = (size_t)(bm + row) * (KD / 8) + it * 4 + seg;
            const size_t gb = (size_t)row * (KD / 8) + it * 4 + seg;
            cp16(d + OFF_A,  gA  + ga);
            cp16(d + OFF_BH, gBh + gb);
            cp16(d + OFF_BL, gBl + gb);
        }
        asm volatile("cp.async.commit_group;" ::: "memory");
    };

    prefetch(0, 0);

    for (int it = 0; it < NITER; it++) {
        const int buf = it & 1;
        if (it + 1 < NITER) {
            prefetch(it + 1, buf ^ 1);
            asm volatile("cp.async.wait_group 1;" ::: "memory");
        } else {
            asm volatile("cp.async.wait_group 0;" ::: "memory");
        }
        __syncthreads();

        const uint32_t base = smb + buf * BUFB;
#pragma unroll
        for (int ks = 0; ks < 2; ks++) {
            uint32_t af[4][4], bhf[2][4], blf[2][4];
#pragma unroll
            for (int mi = 0; mi < 4; mi++) {
                const uint32_t ao = base + OFF_A +
                    (wm + mi * 16 + a_r) * ROWB + ks * 32 + a_c * 16;
                ldsm4(af[mi], ao);
            }
#pragma unroll
            for (int p = 0; p < 2; p++) {
                const uint32_t bo = base + OFF_BH +
                    (wn + p * 16 + b_r4) * ROWB + ks * 32 + b_c4 * 16;
                ldsm4(bhf[p], bo);
                ldsm4(blf[p], bo + (OFF_BL - OFF_BH));
            }
#pragma unroll
            for (int mi = 0; mi < 4; mi++)
#pragma unroll
                for (int ni = 0; ni < 4; ni++) {
                    const uint32_t* bh_ = &bhf[ni >> 1][(ni & 1) * 2];
                    const uint32_t* bl_ = &blf[ni >> 1][(ni & 1) * 2];
                    mma16816h(acc[mi][ni], af[mi], bh_);
                    mma16816h(acc[mi][ni], af[mi], bl_);
                }
        }
        __syncthreads();
    }

    const int er = lane >> 2;
    const int ec = (lane & 3) * 2;
#pragma unroll
    for (int mi = 0; mi < 4; mi++) {
#pragma unroll
        for (int half = 0; half < 2; half++) {
            const int gm = bm + wm + mi * 16 + er + half * 8;
            if (gm < NQ) {
#pragma unroll
                for (int ni = 0; ni < 4; ni++) {
                    const int nn = wn + ni * 8 + ec;
                    float2 v;
                    v.x = acc[mi][ni][half * 2 + 0] + sbias[nn + 0];
                    v.y = acc[mi][ni][half * 2 + 1] + sbias[nn + 1];
                    *reinterpret_cast<float2*>(out + (size_t)gm * COUTV + nn) = v;
                }
            }
        }
    }
}

// ---------------------------------------------------------------------------
extern "C" void kernel_launch(void* const* d_in, const int* in_sizes, int n_in,
                              void* d_out, int out_size)
{
    const float* q    = (const float*)d_in[0];      // [N,3]
    const float* s    = (const float*)d_in[1];      // [M,3]
    const int*   nb   = (const int*)d_in[2];        // [N,H] int32
    const float* x    = (const float*)d_in[3];      // [M,64]
    const float* kp   = (const float*)d_in[4];      // [15,3]
    const float* w    = (const float*)d_in[5];      // [15,64,128]
    const float* bias = (const float*)d_in[6];      // [128]
    float*       out  = (float*)d_out;              // [N,128]

    cudaFuncSetAttribute(kpconv_gemm_mma,
                         cudaFuncAttributeMaxDynamicSharedMemorySize, SMEM_GEMM);

    kpconv_gather<<<NQ / 8, 128>>>(q, s, nb, x, kp, w);
    kpconv_gemm_mma<<<NPAD / 128, 256, SMEM_GEMM>>>(bias, out);
}

// round 9
// speedup vs baseline: 1.9966x; 1.1819x over previous
#include <cuda_runtime.h>
#include <cuda_fp16.h>
#include <cstdint>

// Problem constants
#define NQ    50000
#define MS    50000
#define HN    32
#define KKP   15
#define KP16  16
#define CINV  64
#define COUTV 128
#define KD    1024          // scratch row length (16 kp x 64 cin); >=960 is zero pad
#define KREAL 960
#define NPAD  50048         // 391 * 128
#define NITER 30            // 960 / 32

// ---------------------------------------------------------------------------
// Scratch (device globals; zero-initialized at load -> padding stays zero)
// A = wf fp16, B = W^T fp16 (single-product scheme).
// ---------------------------------------------------------------------------
__device__ __half g_wf[(size_t)NPAD * KD];           // wf  [n][kd] fp16
__device__ __half g_wt[(size_t)COUTV * KD];          // W^T [cout][kd] fp16

// ---------------------------------------------------------------------------
// mma / ldmatrix / cp.async / f32x2 helpers (baseline PTX features only)
// ---------------------------------------------------------------------------
__device__ __forceinline__ void ldsm4(uint32_t* r, uint32_t a) {
    asm volatile("ldmatrix.sync.aligned.m8n8.x4.shared.b16 {%0,%1,%2,%3}, [%4];"
                 : "=r"(r[0]), "=r"(r[1]), "=r"(r[2]), "=r"(r[3]) : "r"(a));
}
__device__ __forceinline__ void mma16816h(float* c, const uint32_t* a, const uint32_t* b) {
    asm volatile(
        "mma.sync.aligned.m16n8k16.row.col.f32.f16.f16.f32 "
        "{%0,%1,%2,%3}, {%4,%5,%6,%7}, {%8,%9}, {%0,%1,%2,%3};"
        : "+f"(c[0]), "+f"(c[1]), "+f"(c[2]), "+f"(c[3])
        : "r"(a[0]), "r"(a[1]), "r"(a[2]), "r"(a[3]), "r"(b[0]), "r"(b[1]));
}
__device__ __forceinline__ void cp16(uint32_t saddr, const void* gaddr) {
    asm volatile("cp.async.cg.shared.global [%0], [%1], 16;"
                 :: "r"(saddr), "l"(gaddr) : "memory");
}
__device__ __forceinline__ unsigned long long fma2(unsigned long long a,
                                                   unsigned long long b,
                                                   unsigned long long c) {
    unsigned long long d;
    asm("fma.rn.f32x2 %0, %1, %2, %3;" : "=l"(d) : "l"(a), "l"(b), "l"(c));
    return d;
}
__device__ __forceinline__ unsigned long long pack2(float lo, float hi) {
    unsigned long long d;
    asm("mov.b64 %0, {%1, %2};" : "=l"(d) : "f"(lo), "f"(hi));
    return d;
}
__device__ __forceinline__ void unpack2(unsigned long long v, float& lo, float& hi) {
    asm("mov.b64 {%0, %1}, %2;" : "=f"(lo), "=f"(hi) : "l"(v));
}

// ---------------------------------------------------------------------------
// Kernel 1: gather + influence weights + H-reduction (f32x2 packed FMA).
// Block = 128 threads = 8 queries x 16 c4-groups. Thread owns 8 k-pairs x 4 ch.
// Blocks 0..1023 additionally prep W^T fp16 (folded weight prep).
// ---------------------------------------------------------------------------
__global__ __launch_bounds__(128) void kpconv_gather(
    const float* __restrict__ q,
    const float* __restrict__ s,
    const int* __restrict__ nb,
    const float* __restrict__ x,
    const float* __restrict__ kp,
    const float* __restrict__ W)
{
    __shared__ int   idxs[8][HN];
    __shared__ float wk[8][HN][KP16];
    __shared__ float kps[48];

    const int t  = threadIdx.x;
    const int n0 = blockIdx.x * 8;
    const int tq = t >> 4;
    const int tc = t & 15;
    const int n  = n0 + tq;

    // folded weight prep: blocks 0..1023 cover 131072 W^T elements
    if (blockIdx.x < 1024) {
        const int id = blockIdx.x * 128 + t;             // 0 .. 131071
        const int kd = id & (KD - 1);
        const int co = id >> 10;
        float v = (kd < KREAL) ? W[kd * COUTV + co] : 0.0f;
        g_wt[id] = __float2half_rn(v);
    }

    if (t < KKP * 3) kps[t] = kp[t];
#pragma unroll
    for (int i = t; i < 8 * HN; i += 128) {
        const int qq = i >> 5, h = i & 31;
        int j = nb[(size_t)(n0 + qq) * HN + h];
        j = j < 0 ? 0 : (j >= MS ? MS - 1 : j);
        idxs[qq][h] = j;
    }
    __syncthreads();

    // influence weights: thread covers h = tc and tc+16 for its query
    {
        const float qx = q[n * 3 + 0];
        const float qy = q[n * 3 + 1];
        const float qz = q[n * 3 + 2];
#pragma unroll
        for (int hh = 0; hh < 2; hh++) {
            const int h = tc + hh * 16;
            const int j = idxs[tq][h];
            const float nx = s[j * 3 + 0] - qx;
            const float ny = s[j * 3 + 1] - qy;
            const float nz = s[j * 3 + 2] - qz;
#pragma unroll
            for (int k = 0; k < KKP; k++) {
                const float dx = nx - kps[k * 3 + 0];
                const float dy = ny - kps[k * 3 + 1];
                const float dz = nz - kps[k * 3 + 2];
                const float d2 = dx * dx + dy * dy + dz * dz;
                const float w  = 1.0f - sqrtf(d2) * (1.0f / 0.072f);
                wk[tq][h][k] = w > 0.0f ? w : 0.0f;
            }
            wk[tq][h][15] = 0.0f;
        }
    }
    __syncthreads();

    // H-reduction: acc[kpair][channel] packed f32x2 (k even .lo, k odd .hi)
    unsigned long long acc[8][4];
#pragma unroll
    for (int p = 0; p < 8; p++)
#pragma unroll
        for (int c = 0; c < 4; c++) acc[p][c] = 0ull;

    const float4* x4 = reinterpret_cast<const float4*>(x);
#pragma unroll 4
    for (int h = 0; h < HN; h++) {
        const int j = idxs[tq][h];
        const float4 xv = x4[(size_t)j * (CINV / 4) + tc];
        unsigned long long xcc[4];
        xcc[0] = pack2(xv.x, xv.x);
        xcc[1] = pack2(xv.y, xv.y);
        xcc[2] = pack2(xv.z, xv.z);
        xcc[3] = pack2(xv.w, xv.w);
        const ulonglong2* wp = reinterpret_cast<const ulonglong2*>(&wk[tq][h][0]);
        unsigned long long wpair[8];
#pragma unroll
        for (int g = 0; g < 4; g++) {
            const ulonglong2 v = wp[g];
            wpair[2 * g + 0] = v.x;
            wpair[2 * g + 1] = v.y;
        }
#pragma unroll
        for (int p = 0; p < 8; p++)
#pragma unroll
            for (int c = 0; c < 4; c++)
                acc[p][c] = fma2(wpair[p], xcc[c], acc[p][c]);
    }

    // store fp16 (uint2 = 4 halves); skip k=15 (stays zero)
    uint2* outv = reinterpret_cast<uint2*>(g_wf);
#pragma unroll
    for (int k = 0; k < KKP; k++) {
        float a[4];
#pragma unroll
        for (int c = 0; c < 4; c++) {
            float lo, hi;
            unpack2(acc[k >> 1][c], lo, hi);
            a[c] = (k & 1) ? hi : lo;
        }
        __half2 p01 = __floats2half2_rn(a[0], a[1]);
        __half2 p23 = __floats2half2_rn(a[2], a[3]);
        const size_t o = (size_t)n * (KD / 4) + k * 16 + tc;
        outv[o] = make_uint2(*reinterpret_cast<uint32_t*>(&p01),
                             *reinterpret_cast<uint32_t*>(&p23));
    }
}

// ---------------------------------------------------------------------------
// Kernel 2: fp16 mma.sync GEMM  out[N,128] = wf[N,960] @ W[960,128] + bias
// Block tile 128x128, 8 warps (64x32 warp tiles), BK=32, cp.async double buffer.
// SINGLE product per k16 (A fp16 x B fp16) -> 3.0M mma, ~40us issue floor.
// ---------------------------------------------------------------------------
#define ROWB  80                 // smem bytes per 32-half row (64B + 16B pad)
#define TILEB (128 * ROWB)       // 10240
#define OFF_A  0
#define OFF_B  TILEB
#define BUFB  (2 * TILEB)        // A, B
#define SMEM_GEMM (2 * BUFB + 512)

__global__ __launch_bounds__(256) void kpconv_gemm_mma(
    const float* __restrict__ bias, float* __restrict__ out)
{
    extern __shared__ char sm[];
    const int t    = threadIdx.x;
    const int lane = t & 31;
    const int wid  = t >> 5;
    const int wm   = (wid >> 2) * 64;   // 0 or 64
    const int wn   = (wid & 3) * 32;    // 0,32,64,96
    const int bm   = blockIdx.x * 128;

    float* sbias = reinterpret_cast<float*>(sm + 2 * BUFB);
    if (t < COUTV) sbias[t] = bias[t];

    const uint32_t smb = (uint32_t)__cvta_generic_to_shared(sm);

    const uint4* gA = reinterpret_cast<const uint4*>(g_wf);
    const uint4* gB = reinterpret_cast<const uint4*>(g_wt);

    float acc[4][4][4];
#pragma unroll
    for (int mi = 0; mi < 4; mi++)
#pragma unroll
        for (int ni = 0; ni < 4; ni++)
#pragma unroll
            for (int e = 0; e < 4; e++) acc[mi][ni][e] = 0.0f;

    // ldmatrix lane address components
    const int a_r  = lane & 15, a_c = lane >> 4;                // A x4
    const int b_r4 = ((lane >> 4) & 1) * 8 + (lane & 7);        // B x4 (2 ni tiles)
    const int b_c4 = (lane >> 3) & 1;

    auto prefetch = [&](int it, int buf) {
        const uint32_t base = smb + buf * BUFB;
#pragma unroll
        for (int j = 0; j < 2; j++) {
            const int row = (t + j * 256) >> 2;
            const int seg = t & 3;
            const uint32_t d = base + row * ROWB + seg * 16;
            const size_t ga = (size_t)(bm + row) * (KD / 8) + it * 4 + seg;
            const size_t gb = (size_t)row * (KD / 8) + it * 4 + seg;
            cp16(d + OFF_A, gA + ga);
            cp16(d + OFF_B, gB + gb);
        }
        asm volatile("cp.async.commit_group;" ::: "memory");
    };

    prefetch(0, 0);

    for (int it = 0; it < NITER; it++) {
        const int buf = it & 1;
        if (it + 1 < NITER) {
            prefetch(it + 1, buf ^ 1);
            asm volatile("cp.async.wait_group 1;" ::: "memory");
        } else {
            asm volatile("cp.async.wait_group 0;" ::: "memory");
        }
        __syncthreads();

        const uint32_t base = smb + buf * BUFB;
#pragma unroll
        for (int ks = 0; ks < 2; ks++) {
            uint32_t af[4][4], bf[2][4];
#pragma unroll
            for (int mi = 0; mi < 4; mi++) {
                const uint32_t ao = base + OFF_A +
                    (wm + mi * 16 + a_r) * ROWB + ks * 32 + a_c * 16;
                ldsm4(af[mi], ao);
            }
#pragma unroll
            for (int p = 0; p < 2; p++) {
                const uint32_t bo = base + OFF_B +
                    (wn + p * 16 + b_r4) * ROWB + ks * 32 + b_c4 * 16;
                ldsm4(bf[p], bo);
            }
#pragma unroll
            for (int mi = 0; mi < 4; mi++)
#pragma unroll
                for (int ni = 0; ni < 4; ni++)
                    mma16816h(acc[mi][ni], af[mi], &bf[ni >> 1][(ni & 1) * 2]);
        }
        __syncthreads();
    }

    const int er = lane >> 2;
    const int ec = (lane & 3) * 2;
#pragma unroll
    for (int mi = 0; mi < 4; mi++) {
#pragma unroll
        for (int half = 0; half < 2; half++) {
            const int gm = bm + wm + mi * 16 + er + half * 8;
            if (gm < NQ) {
#pragma unroll
                for (int ni = 0; ni < 4; ni++) {
                    const int nn = wn + ni * 8 + ec;
                    float2 v;
                    v.x = acc[mi][ni][half * 2 + 0] + sbias[nn + 0];
                    v.y = acc[mi][ni][half * 2 + 1] + sbias[nn + 1];
                    *reinterpret_cast<float2*>(out + (size_t)gm * COUTV + nn) = v;
                }
            }
        }
    }
}

// ---------------------------------------------------------------------------
extern "C" void kernel_launch(void* const* d_in, const int* in_sizes, int n_in,
                              void* d_out, int out_size)
{
    const float* q    = (const float*)d_in[0];      // [N,3]
    const float* s    = (const float*)d_in[1];      // [M,3]
    const int*   nb   = (const int*)d_in[2];        // [N,H] int32
    const float* x    = (const float*)d_in[3];      // [M,64]
    const float* kp   = (const float*)d_in[4];      // [15,3]
    const float* w    = (const float*)d_in[5];      // [15,64,128]
    const float* bias = (const float*)d_in[6];      // [128]
    float*       out  = (float*)d_out;              // [N,128]

    cudaFuncSetAttribute(kpconv_gemm_mma,
                         cudaFuncAttributeMaxDynamicSharedMemorySize, SMEM_GEMM);

    kpconv_gather<<<NQ / 8, 128>>>(q, s, nb, x, kp, w);
    kpconv_gemm_mma<<<NPAD / 128, 256, SMEM_GEMM>>>(bias, out);
}

// round 10
// speedup vs baseline: 2.1552x; 1.0794x over previous
#include <cuda_runtime.h>
#include <cuda_fp16.h>
#include <cstdint>

// Problem constants
#define NQ    50000
#define MS    50000
#define HN    32
#define KKP   15
#define KP16  16
#define CINV  64
#define COUTV 128
#define KD    1024          // scratch row length (16 kp x 64 cin); >=960 is zero pad
#define KREAL 960
#define NPAD  50048         // 391 * 128
#define NITER 30            // 960 / 32

// ---------------------------------------------------------------------------
// Scratch (device globals; zero-initialized at load -> padding stays zero)
// A = wf fp16, B = W^T fp16 (single-product scheme).
// ---------------------------------------------------------------------------
__device__ __half g_wf[(size_t)NPAD * KD];           // wf  [n][kd] fp16
__device__ __half g_wt[(size_t)COUTV * KD];          // W^T [cout][kd] fp16

// ---------------------------------------------------------------------------
// mma / ldmatrix / cp.async / f32x2 helpers (baseline PTX features only)
// ---------------------------------------------------------------------------
__device__ __forceinline__ void ldsm4(uint32_t* r, uint32_t a) {
    asm volatile("ldmatrix.sync.aligned.m8n8.x4.shared.b16 {%0,%1,%2,%3}, [%4];"
                 : "=r"(r[0]), "=r"(r[1]), "=r"(r[2]), "=r"(r[3]) : "r"(a));
}
__device__ __forceinline__ void mma16816h(float* c, const uint32_t* a, const uint32_t* b) {
    asm volatile(
        "mma.sync.aligned.m16n8k16.row.col.f32.f16.f16.f32 "
        "{%0,%1,%2,%3}, {%4,%5,%6,%7}, {%8,%9}, {%0,%1,%2,%3};"
        : "+f"(c[0]), "+f"(c[1]), "+f"(c[2]), "+f"(c[3])
        : "r"(a[0]), "r"(a[1]), "r"(a[2]), "r"(a[3]), "r"(b[0]), "r"(b[1]));
}
__device__ __forceinline__ void cp16(uint32_t saddr, const void* gaddr) {
    asm volatile("cp.async.cg.shared.global [%0], [%1], 16;"
                 :: "r"(saddr), "l"(gaddr) : "memory");
}
__device__ __forceinline__ unsigned long long fma2(unsigned long long a,
                                                   unsigned long long b,
                                                   unsigned long long c) {
    unsigned long long d;
    asm("fma.rn.f32x2 %0, %1, %2, %3;" : "=l"(d) : "l"(a), "l"(b), "l"(c));
    return d;
}
__device__ __forceinline__ unsigned long long pack2(float lo, float hi) {
    unsigned long long d;
    asm("mov.b64 %0, {%1, %2};" : "=l"(d) : "f"(lo), "f"(hi));
    return d;
}
__device__ __forceinline__ void unpack2(unsigned long long v, float& lo, float& hi) {
    asm("mov.b64 {%0, %1}, %2;" : "=f"(lo), "=f"(hi) : "l"(v));
}

// ---------------------------------------------------------------------------
// Kernel 1: gather + influence weights + H-reduction (f32x2 packed FMA).
// Block = 128 threads = 8 queries x 16 c4-groups. Thread owns 8 k-pairs x 4 ch.
// h-loop processed in explicit batches of 8: 8 front-batched LDG.128 (MLP=8)
// then 8 consume steps -> L2 latency exposure /2 vs round 9 (unroll-4).
// Blocks 0..1023 additionally prep W^T fp16 (folded weight prep).
// ---------------------------------------------------------------------------
__global__ __launch_bounds__(128) void kpconv_gather(
    const float* __restrict__ q,
    const float* __restrict__ s,
    const int* __restrict__ nb,
    const float* __restrict__ x,
    const float* __restrict__ kp,
    const float* __restrict__ W)
{
    __shared__ int   idxs[8][HN];
    __shared__ float wk[8][HN][KP16];
    __shared__ float kps[48];

    const int t  = threadIdx.x;
    const int n0 = blockIdx.x * 8;
    const int tq = t >> 4;
    const int tc = t & 15;
    const int n  = n0 + tq;

    // folded weight prep: blocks 0..1023 cover 131072 W^T elements
    if (blockIdx.x < 1024) {
        const int id = blockIdx.x * 128 + t;             // 0 .. 131071
        const int kd = id & (KD - 1);
        const int co = id >> 10;
        float v = (kd < KREAL) ? W[kd * COUTV + co] : 0.0f;
        g_wt[id] = __float2half_rn(v);
    }

    if (t < KKP * 3) kps[t] = kp[t];
#pragma unroll
    for (int i = t; i < 8 * HN; i += 128) {
        const int qq = i >> 5, h = i & 31;
        int j = nb[(size_t)(n0 + qq) * HN + h];
        j = j < 0 ? 0 : (j >= MS ? MS - 1 : j);
        idxs[qq][h] = j;
    }
    __syncthreads();

    // influence weights: thread covers h = tc and tc+16 for its query
    {
        const float qx = q[n * 3 + 0];
        const float qy = q[n * 3 + 1];
        const float qz = q[n * 3 + 2];
#pragma unroll
        for (int hh = 0; hh < 2; hh++) {
            const int h = tc + hh * 16;
            const int j = idxs[tq][h];
            const float nx = s[j * 3 + 0] - qx;
            const float ny = s[j * 3 + 1] - qy;
            const float nz = s[j * 3 + 2] - qz;
#pragma unroll
            for (int k = 0; k < KKP; k++) {
                const float dx = nx - kps[k * 3 + 0];
                const float dy = ny - kps[k * 3 + 1];
                const float dz = nz - kps[k * 3 + 2];
                const float d2 = dx * dx + dy * dy + dz * dz;
                const float w  = 1.0f - sqrtf(d2) * (1.0f / 0.072f);
                wk[tq][h][k] = w > 0.0f ? w : 0.0f;
            }
            wk[tq][h][15] = 0.0f;
        }
    }
    __syncthreads();

    // H-reduction: acc[kpair][channel] packed f32x2 (k even .lo, k odd .hi)
    unsigned long long acc[8][4];
#pragma unroll
    for (int p = 0; p < 8; p++)
#pragma unroll
        for (int c = 0; c < 4; c++) acc[p][c] = 0ull;

    const float4* x4 = reinterpret_cast<const float4*>(x);
#pragma unroll
    for (int b = 0; b < 4; b++) {
        // Phase A: 8 independent gather loads, front-batched (MLP = 8)
        float4 xv[8];
#pragma unroll
        for (int u = 0; u < 8; u++) {
            const int j = idxs[tq][b * 8 + u];
            xv[u] = x4[(size_t)j * (CINV / 4) + tc];
        }
        // Phase B: consume
#pragma unroll
        for (int u = 0; u < 8; u++) {
            const int h = b * 8 + u;
            unsigned long long xcc[4];
            xcc[0] = pack2(xv[u].x, xv[u].x);
            xcc[1] = pack2(xv[u].y, xv[u].y);
            xcc[2] = pack2(xv[u].z, xv[u].z);
            xcc[3] = pack2(xv[u].w, xv[u].w);
            const ulonglong2* wp = reinterpret_cast<const ulonglong2*>(&wk[tq][h][0]);
            unsigned long long wpair[8];
#pragma unroll
            for (int g = 0; g < 4; g++) {
                const ulonglong2 v = wp[g];
                wpair[2 * g + 0] = v.x;
                wpair[2 * g + 1] = v.y;
            }
#pragma unroll
            for (int p = 0; p < 8; p++)
#pragma unroll
                for (int c = 0; c < 4; c++)
                    acc[p][c] = fma2(wpair[p], xcc[c], acc[p][c]);
        }
    }

    // store fp16 (uint2 = 4 halves); skip k=15 (stays zero)
    uint2* outv = reinterpret_cast<uint2*>(g_wf);
#pragma unroll
    for (int k = 0; k < KKP; k++) {
        float a[4];
#pragma unroll
        for (int c = 0; c < 4; c++) {
            float lo, hi;
            unpack2(acc[k >> 1][c], lo, hi);
            a[c] = (k & 1) ? hi : lo;
        }
        __half2 p01 = __floats2half2_rn(a[0], a[1]);
        __half2 p23 = __floats2half2_rn(a[2], a[3]);
        const size_t o = (size_t)n * (KD / 4) + k * 16 + tc;
        outv[o] = make_uint2(*reinterpret_cast<uint32_t*>(&p01),
                             *reinterpret_cast<uint32_t*>(&p23));
    }
}

// ---------------------------------------------------------------------------
// Kernel 2: fp16 mma.sync GEMM  out[N,128] = wf[N,960] @ W[960,128] + bias
// (byte-identical to round 9 — measured at tail-adjusted mma roofline 53.5us)
// ---------------------------------------------------------------------------
#define ROWB  80                 // smem bytes per 32-half row (64B + 16B pad)
#define TILEB (128 * ROWB)       // 10240
#define OFF_A  0
#define OFF_B  TILEB
#define BUFB  (2 * TILEB)        // A, B
#define SMEM_GEMM (2 * BUFB + 512)

__global__ __launch_bounds__(256) void kpconv_gemm_mma(
    const float* __restrict__ bias, float* __restrict__ out)
{
    extern __shared__ char sm[];
    const int t    = threadIdx.x;
    const int lane = t & 31;
    const int wid  = t >> 5;
    const int wm   = (wid >> 2) * 64;   // 0 or 64
    const int wn   = (wid & 3) * 32;    // 0,32,64,96
    const int bm   = blockIdx.x * 128;

    float* sbias = reinterpret_cast<float*>(sm + 2 * BUFB);
    if (t < COUTV) sbias[t] = bias[t];

    const uint32_t smb = (uint32_t)__cvta_generic_to_shared(sm);

    const uint4* gA = reinterpret_cast<const uint4*>(g_wf);
    const uint4* gB = reinterpret_cast<const uint4*>(g_wt);

    float acc[4][4][4];
#pragma unroll
    for (int mi = 0; mi < 4; mi++)
#pragma unroll
        for (int ni = 0; ni < 4; ni++)
#pragma unroll
            for (int e = 0; e < 4; e++) acc[mi][ni][e] = 0.0f;

    const int a_r  = lane & 15, a_c = lane >> 4;
    const int b_r4 = ((lane >> 4) & 1) * 8 + (lane & 7);
    const int b_c4 = (lane >> 3) & 1;

    auto prefetch = [&](int it, int buf) {
        const uint32_t base = smb + buf * BUFB;
#pragma unroll
        for (int j = 0; j < 2; j++) {
            const int row = (t + j * 256) >> 2;
            const int seg = t & 3;
            const uint32_t d = base + row * ROWB + seg * 16;
            const size_t ga = (size_t)(bm + row) * (KD / 8) + it * 4 + seg;
            const size_t gb = (size_t)row * (KD / 8) + it * 4 + seg;
            cp16(d + OFF_A, gA + ga);
            cp16(d + OFF_B, gB + gb);
        }
        asm volatile("cp.async.commit_group;" ::: "memory");
    };

    prefetch(0, 0);

    for (int it = 0; it < NITER; it++) {
        const int buf = it & 1;
        if (it + 1 < NITER) {
            prefetch(it + 1, buf ^ 1);
            asm volatile("cp.async.wait_group 1;" ::: "memory");
        } else {
            asm volatile("cp.async.wait_group 0;" ::: "memory");
        }
        __syncthreads();

        const uint32_t base = smb + buf * BUFB;
#pragma unroll
        for (int ks = 0; ks < 2; ks++) {
            uint32_t af[4][4], bf[2][4];
#pragma unroll
            for (int mi = 0; mi < 4; mi++) {
                const uint32_t ao = base + OFF_A +
                    (wm + mi * 16 + a_r) * ROWB + ks * 32 + a_c * 16;
                ldsm4(af[mi], ao);
            }
#pragma unroll
            for (int p = 0; p < 2; p++) {
                const uint32_t bo = base + OFF_B +
                    (wn + p * 16 + b_r4) * ROWB + ks * 32 + b_c4 * 16;
                ldsm4(bf[p], bo);
            }
#pragma unroll
            for (int mi = 0; mi < 4; mi++)
#pragma unroll
                for (int ni = 0; ni < 4; ni++)
                    mma16816h(acc[mi][ni], af[mi], &bf[ni >> 1][(ni & 1) * 2]);
        }
        __syncthreads();
    }

    const int er = lane >> 2;
    const int ec = (lane & 3) * 2;
#pragma unroll
    for (int mi = 0; mi < 4; mi++) {
#pragma unroll
        for (int half = 0; half < 2; half++) {
            const int gm = bm + wm + mi * 16 + er + half * 8;
            if (gm < NQ) {
#pragma unroll
                for (int ni = 0; ni < 4; ni++) {
                    const int nn = wn + ni * 8 + ec;
                    float2 v;
                    v.x = acc[mi][ni][half * 2 + 0] + sbias[nn + 0];
                    v.y = acc[mi][ni][half * 2 + 1] + sbias[nn + 1];
                    *reinterpret_cast<float2*>(out + (size_t)gm * COUTV + nn) = v;
                }
            }
        }
    }
}

// ---------------------------------------------------------------------------
extern "C" void kernel_launch(void* const* d_in, const int* in_sizes, int n_in,
                              void* d_out, int out_size)
{
    const float* q    = (const float*)d_in[0];      // [N,3]
    const float* s    = (const float*)d_in[1];      // [M,3]
    const int*   nb   = (const int*)d_in[2];        // [N,H] int32
    const float* x    = (const float*)d_in[3];      // [M,64]
    const float* kp   = (const float*)d_in[4];      // [15,3]
    const float* w    = (const float*)d_in[5];      // [15,64,128]
    const float* bias = (const float*)d_in[6];      // [128]
    float*       out  = (float*)d_out;              // [N,128]

    cudaFuncSetAttribute(kpconv_gemm_mma,
                         cudaFuncAttributeMaxDynamicSharedMemorySize, SMEM_GEMM);

    kpconv_gather<<<NQ / 8, 128>>>(q, s, nb, x, kp, w);
    kpconv_gemm_mma<<<NPAD / 128, 256, SMEM_GEMM>>>(bias, out);
}